// round 15
// baseline (speedup 1.0000x reference)
#include <cuda_runtime.h>
#include <cuda_fp16.h>
#include <cstdint>

#define B_    4
#define N_    16384
#define C_    64
#define K_    16
#define O_    64
#define RTOT  (B_ * N_)          // 65536 rows
#define TOTSAMP 1048576.0f
#define BN_EPS 1e-5f

__device__ __align__(16) __half g_uh [RTOT * O_];  // fp16: x @ (W1-W2)^T
__device__ __align__(16) __half g_vh [RTOT * O_];  // fp16: x @ W2^T
__device__ __align__(16) __half g_mxh[RTOT * O_];  // fp16: u + max_k v
__device__ __align__(16) __half g_mnh[RTOT * O_];  // fp16: u + min_k v
__device__ float g_sum[O_];
__device__ float g_sq[O_];
__device__ int   g_gneg;
// fp16 fragment-ordered split weights: [ks(4)][t(16)][lane(32)] uint2 {b0,b1}
__device__ __align__(16) uint2 g_Bh[4 * 16 * 32];
__device__ __align__(16) uint2 g_Bl[4 * 16 * 32];

// ---------------------------------------------------------------------------
// fp16 mma helper (sm_80 baseline PTX)
// ---------------------------------------------------------------------------
__device__ __forceinline__ void mma_f16(float d[4], const uint32_t a[4],
                                        const uint32_t b0, const uint32_t b1) {
    asm volatile(
        "mma.sync.aligned.m16n8k16.row.col.f32.f16.f16.f32 "
        "{%0,%1,%2,%3}, {%4,%5,%6,%7}, {%8,%9}, {%0,%1,%2,%3};"
        : "+f"(d[0]), "+f"(d[1]), "+f"(d[2]), "+f"(d[3])
        : "r"(a[0]), "r"(a[1]), "r"(a[2]), "r"(a[3]), "r"(b0), "r"(b1));
}

__device__ __forceinline__ float wprime(const float* w, int n, int k) {
    return (n < 64) ? (w[n * 128 + k] - w[n * 128 + 64 + k])
                    : w[(n - 64) * 128 + 64 + k];
}

// ---------------------------------------------------------------------------
// K0: pre-split weights into fp16 hi/lo fragment order + zero stats + gneg.
// ---------------------------------------------------------------------------
__global__ void k_prep(const float* __restrict__ w,
                       const float* __restrict__ gamma) {
    int i = blockIdx.x * 256 + threadIdx.x;
    if (i < 64) { g_sum[i] = 0.f; g_sq[i] = 0.f; }
    if (i == 64) {
        int neg = 0;
        for (int o = 0; o < O_; o++) neg |= (gamma[o] < 0.f);
        g_gneg = neg;
    }
    if (i >= 4 * 16 * 32) return;
    int l  = i & 31;
    int t  = (i >> 5) & 15;
    int ks = i >> 9;
    int n = t * 8 + (l >> 2);
    int k = ks * 16 + (l & 3) * 2;

    float v0 = wprime(w, n, k),     v1 = wprime(w, n, k + 1);
    float v2 = wprime(w, n, k + 8), v3 = wprime(w, n, k + 9);

    __half2 h01 = __floats2half2_rn(v0, v1);
    __half2 h23 = __floats2half2_rn(v2, v3);
    float2 f01 = __half22float2(h01);
    float2 f23 = __half22float2(h23);
    __half2 l01 = __floats2half2_rn(v0 - f01.x, v1 - f01.y);
    __half2 l23 = __floats2half2_rn(v2 - f23.x, v3 - f23.y);

    g_Bh[i] = make_uint2(*(uint32_t*)&h01, *(uint32_t*)&h23);
    g_Bl[i] = make_uint2(*(uint32_t*)&l01, *(uint32_t*)&l23);
}

// ---------------------------------------------------------------------------
// K1: [u|v] = x @ [ (W1-W2)^T | W2^T ] — fp16 m16n8k16, 2-term split (3 MMAs).
// CTA: 64 rows x 128 cols, 8 warps; cg=0 -> u, cg=1 -> v, both fp16 out.
// ---------------------------------------------------------------------------
#define XPITCH 68
__global__ __launch_bounds__(256, 3) void k_gemm(const float* __restrict__ x) {
    __shared__ float sX[64][XPITCH];

    int tid = threadIdx.x;
    int lane = tid & 31, wid = tid >> 5;
    int rg = wid & 3, cg = wid >> 2;

    int rowBase = blockIdx.x * 64;
    const float4* x4 = (const float4*)(x + (size_t)rowBase * 64);
    for (int i = tid; i < 64 * 16; i += 256) {
        int r = i >> 4, c4 = i & 15;
        float4 v = x4[i];
        float* p = &sX[r][c4 * 4];
        p[0] = v.x; p[1] = v.y; p[2] = v.z; p[3] = v.w;
    }
    __syncthreads();

    float acc[8][4] = {};
    int arow = rg * 16 + (lane >> 2);
    const uint2* bhBase = g_Bh + cg * 8 * 32 + lane;
    const uint2* blBase = g_Bl + cg * 8 * 32 + lane;

#pragma unroll
    for (int ks = 0; ks < 4; ks++) {
        uint32_t ah[4], al[4];
        {
            int kc = ks * 16 + (lane & 3) * 2;
            float2 p00 = *(const float2*)&sX[arow][kc];
            float2 p10 = *(const float2*)&sX[arow + 8][kc];
            float2 p01 = *(const float2*)&sX[arow][kc + 8];
            float2 p11 = *(const float2*)&sX[arow + 8][kc + 8];
            __half2 h00 = __floats2half2_rn(p00.x, p00.y);
            __half2 h10 = __floats2half2_rn(p10.x, p10.y);
            __half2 h01 = __floats2half2_rn(p01.x, p01.y);
            __half2 h11 = __floats2half2_rn(p11.x, p11.y);
            float2 f00 = __half22float2(h00), f10 = __half22float2(h10);
            float2 f01 = __half22float2(h01), f11 = __half22float2(h11);
            __half2 l00 = __floats2half2_rn(p00.x - f00.x, p00.y - f00.y);
            __half2 l10 = __floats2half2_rn(p10.x - f10.x, p10.y - f10.y);
            __half2 l01 = __floats2half2_rn(p01.x - f01.x, p01.y - f01.y);
            __half2 l11 = __floats2half2_rn(p11.x - f11.x, p11.y - f11.y);
            ah[0] = *(uint32_t*)&h00; al[0] = *(uint32_t*)&l00;
            ah[1] = *(uint32_t*)&h10; al[1] = *(uint32_t*)&l10;
            ah[2] = *(uint32_t*)&h01; al[2] = *(uint32_t*)&l01;
            ah[3] = *(uint32_t*)&h11; al[3] = *(uint32_t*)&l11;
        }
        const uint2* bh = bhBase + ks * 16 * 32;
        const uint2* bl = blBase + ks * 16 * 32;
#pragma unroll
        for (int t = 0; t < 8; t++) {
            uint2 H = __ldg(bh + t * 32);
            uint2 L = __ldg(bl + t * 32);
            mma_f16(acc[t], ah, H.x, H.y);
            mma_f16(acc[t], ah, L.x, L.y);
            mma_f16(acc[t], al, H.x, H.y);
        }
    }

    __half* dst = cg ? g_vh : g_uh;
    int row = rowBase + rg * 16 + (lane >> 2);
    int col = (lane & 3) * 2;
#pragma unroll
    for (int t = 0; t < 8; t++) {
        *(__half2*)(dst + (size_t)row * 64 + t * 8 + col) =
            __floats2half2_rn(acc[t][0], acc[t][1]);
        *(__half2*)(dst + (size_t)(row + 8) * 64 + t * 8 + col) =
            __floats2half2_rn(acc[t][2], acc[t][3]);
    }
}

// ---------------------------------------------------------------------------
// K2: gather: smem-staged idx, fp16 u/v in, fp16 mx/mn out, min-skip.
// ---------------------------------------------------------------------------
__global__ __launch_bounds__(256) void k_gather(const int* __restrict__ idx) {
    __shared__ int sIdx[8][256];
    __shared__ float ssum[O_], ssq[O_];

    int tid  = threadIdx.x;
    int lane = tid & 31;
    int half = lane >> 4;
    int c4   = lane & 15;
    int w    = tid >> 5;
    int warpId = blockIdx.x * 8 + w;
    int pbase  = warpId * 16;
    int b = pbase >> 14;
    const uint2* vb = (const uint2*)(g_vh + (size_t)b * N_ * O_);

    {
        const int4* src = (const int4*)(idx + (size_t)pbase * K_);
        ((int4*)sIdx[w])[lane]      = src[lane];
        ((int4*)sIdx[w])[lane + 32] = src[lane + 32];
    }
    __syncwarp();

    const int gneg = g_gneg;

    float4 cs1 = {0, 0, 0, 0}, cs2 = {0, 0, 0, 0};

    for (int p = 0; p < 16; ++p) {
        int point = pbase + p;
        const int* sip = &sIdx[w][p * 16];

        uint2 uraw = __ldg((const uint2*)(g_uh + (size_t)point * O_) + c4);
        float2 u01 = __half22float2(*(__half2*)&uraw.x);
        float2 u23 = __half22float2(*(__half2*)&uraw.y);
        float4 u = make_float4(u01.x, u01.y, u23.x, u23.y);

        float4 mx = make_float4(-3.4e38f, -3.4e38f, -3.4e38f, -3.4e38f);
        float4 mn = make_float4( 3.4e38f,  3.4e38f,  3.4e38f,  3.4e38f);
        float4 s1 = {0, 0, 0, 0}, s2 = {0, 0, 0, 0};

        int j[8];
#pragma unroll
        for (int s = 0; s < 8; s++) j[s] = sip[2 * s + half];

        if (!gneg) {
#pragma unroll
            for (int s = 0; s < 8; s++) {
                uint2 raw = __ldg(vb + (size_t)j[s] * 16 + c4);
                float2 v01 = __half22float2(*(__half2*)&raw.x);
                float2 v23 = __half22float2(*(__half2*)&raw.y);
                mx.x = fmaxf(mx.x, v01.x); s1.x += v01.x; s2.x = fmaf(v01.x, v01.x, s2.x);
                mx.y = fmaxf(mx.y, v01.y); s1.y += v01.y; s2.y = fmaf(v01.y, v01.y, s2.y);
                mx.z = fmaxf(mx.z, v23.x); s1.z += v23.x; s2.z = fmaf(v23.x, v23.x, s2.z);
                mx.w = fmaxf(mx.w, v23.y); s1.w += v23.y; s2.w = fmaf(v23.y, v23.y, s2.w);
            }
        } else {
#pragma unroll
            for (int s = 0; s < 8; s++) {
                uint2 raw = __ldg(vb + (size_t)j[s] * 16 + c4);
                float2 v01 = __half22float2(*(__half2*)&raw.x);
                float2 v23 = __half22float2(*(__half2*)&raw.y);
                mx.x = fmaxf(mx.x, v01.x); mn.x = fminf(mn.x, v01.x); s1.x += v01.x; s2.x = fmaf(v01.x, v01.x, s2.x);
                mx.y = fmaxf(mx.y, v01.y); mn.y = fminf(mn.y, v01.y); s1.y += v01.y; s2.y = fmaf(v01.y, v01.y, s2.y);
                mx.z = fmaxf(mx.z, v23.x); mn.z = fminf(mn.z, v23.x); s1.z += v23.x; s2.z = fmaf(v23.x, v23.x, s2.z);
                mx.w = fmaxf(mx.w, v23.y); mn.w = fminf(mn.w, v23.y); s1.w += v23.y; s2.w = fmaf(v23.y, v23.y, s2.w);
            }
        }

        mx.x = fmaxf(mx.x, __shfl_xor_sync(0xffffffffu, mx.x, 16));
        mx.y = fmaxf(mx.y, __shfl_xor_sync(0xffffffffu, mx.y, 16));
        mx.z = fmaxf(mx.z, __shfl_xor_sync(0xffffffffu, mx.z, 16));
        mx.w = fmaxf(mx.w, __shfl_xor_sync(0xffffffffu, mx.w, 16));
        if (half == 0) {
            __half2 a01 = __floats2half2_rn(u.x + mx.x, u.y + mx.y);
            __half2 a23 = __floats2half2_rn(u.z + mx.z, u.w + mx.w);
            ((uint2*)(g_mxh + (size_t)point * O_))[c4] =
                make_uint2(*(uint32_t*)&a01, *(uint32_t*)&a23);
        }
        if (gneg) {
            mn.x = fminf(mn.x, __shfl_xor_sync(0xffffffffu, mn.x, 16));
            mn.y = fminf(mn.y, __shfl_xor_sync(0xffffffffu, mn.y, 16));
            mn.z = fminf(mn.z, __shfl_xor_sync(0xffffffffu, mn.z, 16));
            mn.w = fminf(mn.w, __shfl_xor_sync(0xffffffffu, mn.w, 16));
            if (half == 0) {
                __half2 a01 = __floats2half2_rn(u.x + mn.x, u.y + mn.y);
                __half2 a23 = __floats2half2_rn(u.z + mn.z, u.w + mn.w);
                ((uint2*)(g_mnh + (size_t)point * O_))[c4] =
                    make_uint2(*(uint32_t*)&a01, *(uint32_t*)&a23);
            }
        }

        cs1.x += 8.f * u.x + s1.x;  cs2.x += fmaf(8.f * u.x, u.x, fmaf(2.f * u.x, s1.x, s2.x));
        cs1.y += 8.f * u.y + s1.y;  cs2.y += fmaf(8.f * u.y, u.y, fmaf(2.f * u.y, s1.y, s2.y));
        cs1.z += 8.f * u.z + s1.z;  cs2.z += fmaf(8.f * u.z, u.z, fmaf(2.f * u.z, s1.z, s2.z));
        cs1.w += 8.f * u.w + s1.w;  cs2.w += fmaf(8.f * u.w, u.w, fmaf(2.f * u.w, s1.w, s2.w));
    }

    if (tid < O_) { ssum[tid] = 0.f; ssq[tid] = 0.f; }
    __syncthreads();
    int cb = c4 * 4;
    atomicAdd(&ssum[cb + 0], cs1.x); atomicAdd(&ssq[cb + 0], cs2.x);
    atomicAdd(&ssum[cb + 1], cs1.y); atomicAdd(&ssq[cb + 1], cs2.y);
    atomicAdd(&ssum[cb + 2], cs1.z); atomicAdd(&ssq[cb + 2], cs2.z);
    atomicAdd(&ssum[cb + 3], cs1.w); atomicAdd(&ssq[cb + 3], cs2.w);
    __syncthreads();
    if (tid < O_) {
        atomicAdd(&g_sum[tid], ssum[tid]);
        atomicAdd(&g_sq[tid],  ssq[tid]);
    }
}

// ---------------------------------------------------------------------------
// K3: fused stats + epilogue; fp16 mx/mn input, fp32 output, 8 iters/thread.
// ---------------------------------------------------------------------------
#define OUT_ITERS 8
#define OUT_STEP  (512 * 256)      // grid * block, in 4-channel groups
__global__ __launch_bounds__(256) void k_out(const float* __restrict__ gamma,
                                             const float* __restrict__ beta,
                                             float* __restrict__ out) {
    __shared__ __align__(16) float sc[O_];
    __shared__ __align__(16) float sh[O_];
    int tid = threadIdx.x;
    if (tid < O_) {
        float inv  = 1.0f / TOTSAMP;
        float mean = g_sum[tid] * inv;
        float var  = g_sq[tid] * inv - mean * mean;
        float s    = rsqrtf(var + BN_EPS) * gamma[tid];
        sc[tid] = s;
        sh[tid] = beta[tid] - mean * s;
    }
    __syncthreads();

    size_t base = (size_t)blockIdx.x * 256 + tid;
    int o4 = (int)(base & 15);
    float4 s4 = ((const float4*)sc)[o4];
    float4 b4 = ((const float4*)sh)[o4];
    int gneg = g_gneg;

#pragma unroll
    for (int it = 0; it < OUT_ITERS; it++) {
        size_t i4 = base + (size_t)it * OUT_STEP;
        uint2 rawA = __ldg((const uint2*)g_mxh + i4);
        float2 a01 = __half22float2(*(__half2*)&rawA.x);
        float2 a23 = __half22float2(*(__half2*)&rawA.y);
        float4 m = make_float4(a01.x, a01.y, a23.x, a23.y);
        if (gneg) {
            uint2 rawC = __ldg((const uint2*)g_mnh + i4);
            float2 c01 = __half22float2(*(__half2*)&rawC.x);
            float2 c23 = __half22float2(*(__half2*)&rawC.y);
            m.x = (s4.x >= 0.f) ? m.x : c01.x;
            m.y = (s4.y >= 0.f) ? m.y : c01.y;
            m.z = (s4.z >= 0.f) ? m.z : c23.x;
            m.w = (s4.w >= 0.f) ? m.w : c23.y;
        }
        float4 r;
        r.x = fmaxf(fmaf(m.x, s4.x, b4.x), 0.f);
        r.y = fmaxf(fmaf(m.y, s4.y, b4.y), 0.f);
        r.z = fmaxf(fmaf(m.z, s4.z, b4.z), 0.f);
        r.w = fmaxf(fmaf(m.w, s4.w, b4.w), 0.f);
        ((float4*)out)[i4] = r;
    }
}

extern "C" void kernel_launch(void* const* d_in, const int* in_sizes, int n_in,
                              void* d_out, int out_size) {
    const float* x     = (const float*)d_in[0];
    const int*   idx   = (const int*)  d_in[1];
    const float* w     = (const float*)d_in[2];
    const float* gamma = (const float*)d_in[3];
    const float* beta  = (const float*)d_in[4];
    float* out = (float*)d_out;

    k_prep  <<<8, 256>>>(w, gamma);
    k_gemm  <<<RTOT / 64, 256>>>(x);
    k_gather<<<RTOT / (8 * 16), 256>>>(idx);
    k_out   <<<512, 256>>>(gamma, beta, out);
}

// round 16
// speedup vs baseline: 1.0668x; 1.0668x over previous
#include <cuda_runtime.h>
#include <cuda_fp16.h>
#include <cstdint>

#define B_    4
#define N_    16384
#define C_    64
#define K_    16
#define O_    64
#define RTOT  (B_ * N_)          // 65536 rows
#define TOTSAMP 1048576.0f
#define BN_EPS 1e-5f

__device__ __align__(16) float  g_u  [RTOT * O_];  // fp32
__device__ __align__(16) __half g_vh [RTOT * O_];  // fp16 gather operand
__device__ __align__(16) __half g_mxh[RTOT * O_];  // fp16: u + max_k v
__device__ __align__(16) __half g_mnh[RTOT * O_];  // fp16: u + min_k v
__device__ float g_sum[O_];
__device__ float g_sq[O_];
__device__ int   g_gneg;
// fp16 fragment-ordered split weights: [ks(4)][t(16)][lane(32)] uint2 {b0,b1}
__device__ __align__(16) uint2 g_Bh[4 * 16 * 32];
__device__ __align__(16) uint2 g_Bl[4 * 16 * 32];

// ---------------------------------------------------------------------------
// fp16 mma helper (sm_80 baseline PTX)
// ---------------------------------------------------------------------------
__device__ __forceinline__ void mma_f16(float d[4], const uint32_t a[4],
                                        const uint32_t b0, const uint32_t b1) {
    asm volatile(
        "mma.sync.aligned.m16n8k16.row.col.f32.f16.f16.f32 "
        "{%0,%1,%2,%3}, {%4,%5,%6,%7}, {%8,%9}, {%0,%1,%2,%3};"
        : "+f"(d[0]), "+f"(d[1]), "+f"(d[2]), "+f"(d[3])
        : "r"(a[0]), "r"(a[1]), "r"(a[2]), "r"(a[3]), "r"(b0), "r"(b1));
}

__device__ __forceinline__ float wprime(const float* w, int n, int k) {
    return (n < 64) ? (w[n * 128 + k] - w[n * 128 + 64 + k])
                    : w[(n - 64) * 128 + 64 + k];
}

// ---------------------------------------------------------------------------
// K0: pre-split weights into fp16 hi/lo fragment order + zero stats + gneg.
// ---------------------------------------------------------------------------
__global__ void k_prep(const float* __restrict__ w,
                       const float* __restrict__ gamma) {
    int i = blockIdx.x * 256 + threadIdx.x;
    if (i < 64) { g_sum[i] = 0.f; g_sq[i] = 0.f; }
    if (i == 64) {
        int neg = 0;
        for (int o = 0; o < O_; o++) neg |= (gamma[o] < 0.f);
        g_gneg = neg;
    }
    if (i >= 4 * 16 * 32) return;
    int l  = i & 31;
    int t  = (i >> 5) & 15;
    int ks = i >> 9;
    int n = t * 8 + (l >> 2);
    int k = ks * 16 + (l & 3) * 2;

    float v0 = wprime(w, n, k),     v1 = wprime(w, n, k + 1);
    float v2 = wprime(w, n, k + 8), v3 = wprime(w, n, k + 9);

    __half2 h01 = __floats2half2_rn(v0, v1);
    __half2 h23 = __floats2half2_rn(v2, v3);
    float2 f01 = __half22float2(h01);
    float2 f23 = __half22float2(h23);
    __half2 l01 = __floats2half2_rn(v0 - f01.x, v1 - f01.y);
    __half2 l23 = __floats2half2_rn(v2 - f23.x, v3 - f23.y);

    g_Bh[i] = make_uint2(*(uint32_t*)&h01, *(uint32_t*)&h23);
    g_Bl[i] = make_uint2(*(uint32_t*)&l01, *(uint32_t*)&l23);
}

// ---------------------------------------------------------------------------
// K1: [u|v] GEMM, fp16 m16n8k16 2-term split. PDL: stages the x tile
// (independent of k_prep) before cudaGridDependencySynchronize().
// ---------------------------------------------------------------------------
#define XPITCH 68
__global__ __launch_bounds__(256, 3) void k_gemm(const float* __restrict__ x) {
    __shared__ float sX[64][XPITCH];

    int tid = threadIdx.x;
    int lane = tid & 31, wid = tid >> 5;
    int rg = wid & 3, cg = wid >> 2;

    int rowBase = blockIdx.x * 64;
    const float4* x4 = (const float4*)(x + (size_t)rowBase * 64);
    for (int i = tid; i < 64 * 16; i += 256) {
        int r = i >> 4, c4 = i & 15;
        float4 v = x4[i];
        float* p = &sX[r][c4 * 4];
        p[0] = v.x; p[1] = v.y; p[2] = v.z; p[3] = v.w;
    }

#if __CUDA_ARCH__ >= 900
    cudaGridDependencySynchronize();   // wait for k_prep's weight fragments
#endif
    __syncthreads();

    float acc[8][4] = {};
    int arow = rg * 16 + (lane >> 2);
    const uint2* bhBase = g_Bh + cg * 8 * 32 + lane;
    const uint2* blBase = g_Bl + cg * 8 * 32 + lane;

#pragma unroll
    for (int ks = 0; ks < 4; ks++) {
        uint32_t ah[4], al[4];
        {
            int kc = ks * 16 + (lane & 3) * 2;
            float2 p00 = *(const float2*)&sX[arow][kc];
            float2 p10 = *(const float2*)&sX[arow + 8][kc];
            float2 p01 = *(const float2*)&sX[arow][kc + 8];
            float2 p11 = *(const float2*)&sX[arow + 8][kc + 8];
            __half2 h00 = __floats2half2_rn(p00.x, p00.y);
            __half2 h10 = __floats2half2_rn(p10.x, p10.y);
            __half2 h01 = __floats2half2_rn(p01.x, p01.y);
            __half2 h11 = __floats2half2_rn(p11.x, p11.y);
            float2 f00 = __half22float2(h00), f10 = __half22float2(h10);
            float2 f01 = __half22float2(h01), f11 = __half22float2(h11);
            __half2 l00 = __floats2half2_rn(p00.x - f00.x, p00.y - f00.y);
            __half2 l10 = __floats2half2_rn(p10.x - f10.x, p10.y - f10.y);
            __half2 l01 = __floats2half2_rn(p01.x - f01.x, p01.y - f01.y);
            __half2 l11 = __floats2half2_rn(p11.x - f11.x, p11.y - f11.y);
            ah[0] = *(uint32_t*)&h00; al[0] = *(uint32_t*)&l00;
            ah[1] = *(uint32_t*)&h10; al[1] = *(uint32_t*)&l10;
            ah[2] = *(uint32_t*)&h01; al[2] = *(uint32_t*)&l01;
            ah[3] = *(uint32_t*)&h11; al[3] = *(uint32_t*)&l11;
        }
        const uint2* bh = bhBase + ks * 16 * 32;
        const uint2* bl = blBase + ks * 16 * 32;
#pragma unroll
        for (int t = 0; t < 8; t++) {
            uint2 H = __ldg(bh + t * 32);
            uint2 L = __ldg(bl + t * 32);
            mma_f16(acc[t], ah, H.x, H.y);
            mma_f16(acc[t], ah, L.x, L.y);
            mma_f16(acc[t], al, H.x, H.y);
        }
    }

    int row = rowBase + rg * 16 + (lane >> 2);
    int col = (lane & 3) * 2;
    if (cg == 0) {
#pragma unroll
        for (int t = 0; t < 8; t++) {
            *(float2*)(g_u + (size_t)row * 64 + t * 8 + col) =
                make_float2(acc[t][0], acc[t][1]);
            *(float2*)(g_u + (size_t)(row + 8) * 64 + t * 8 + col) =
                make_float2(acc[t][2], acc[t][3]);
        }
    } else {
#pragma unroll
        for (int t = 0; t < 8; t++) {
            *(__half2*)(g_vh + (size_t)row * 64 + t * 8 + col) =
                __floats2half2_rn(acc[t][0], acc[t][1]);
            *(__half2*)(g_vh + (size_t)(row + 8) * 64 + t * 8 + col) =
                __floats2half2_rn(acc[t][2], acc[t][3]);
        }
    }
}

// ---------------------------------------------------------------------------
// K2: gather. PDL: stages idx (reads the INPUT, independent of GEMM) before
// cudaGridDependencySynchronize().
// ---------------------------------------------------------------------------
__global__ __launch_bounds__(256) void k_gather(const int* __restrict__ idx) {
    __shared__ int sIdx[8][256];
    __shared__ float ssum[O_], ssq[O_];

    int tid  = threadIdx.x;
    int lane = tid & 31;
    int half = lane >> 4;
    int c4   = lane & 15;
    int w    = tid >> 5;
    int warpId = blockIdx.x * 8 + w;
    int pbase  = warpId * 16;
    int b = pbase >> 14;
    const uint2* vb = (const uint2*)(g_vh + (size_t)b * N_ * O_);

    {
        const int4* src = (const int4*)(idx + (size_t)pbase * K_);
        ((int4*)sIdx[w])[lane]      = src[lane];
        ((int4*)sIdx[w])[lane + 32] = src[lane + 32];
    }
    if (tid < O_) { ssum[tid] = 0.f; ssq[tid] = 0.f; }

#if __CUDA_ARCH__ >= 900
    cudaGridDependencySynchronize();   // wait for k_gemm's u/v
#endif
    __syncwarp();

    const int gneg = g_gneg;

    float4 cs1 = {0, 0, 0, 0}, cs2 = {0, 0, 0, 0};

    for (int p = 0; p < 16; ++p) {
        int point = pbase + p;
        const int* sip = &sIdx[w][p * 16];

        float4 u = __ldg((const float4*)(g_u + (size_t)point * O_) + c4);

        float4 mx = make_float4(-3.4e38f, -3.4e38f, -3.4e38f, -3.4e38f);
        float4 mn = make_float4( 3.4e38f,  3.4e38f,  3.4e38f,  3.4e38f);
        float4 s1 = {0, 0, 0, 0}, s2 = {0, 0, 0, 0};

        int j[8];
#pragma unroll
        for (int s = 0; s < 8; s++) j[s] = sip[2 * s + half];

        if (!gneg) {
#pragma unroll
            for (int s = 0; s < 8; s++) {
                uint2 raw = __ldg(vb + (size_t)j[s] * 16 + c4);
                float2 v01 = __half22float2(*(__half2*)&raw.x);
                float2 v23 = __half22float2(*(__half2*)&raw.y);
                mx.x = fmaxf(mx.x, v01.x); s1.x += v01.x; s2.x = fmaf(v01.x, v01.x, s2.x);
                mx.y = fmaxf(mx.y, v01.y); s1.y += v01.y; s2.y = fmaf(v01.y, v01.y, s2.y);
                mx.z = fmaxf(mx.z, v23.x); s1.z += v23.x; s2.z = fmaf(v23.x, v23.x, s2.z);
                mx.w = fmaxf(mx.w, v23.y); s1.w += v23.y; s2.w = fmaf(v23.y, v23.y, s2.w);
            }
        } else {
#pragma unroll
            for (int s = 0; s < 8; s++) {
                uint2 raw = __ldg(vb + (size_t)j[s] * 16 + c4);
                float2 v01 = __half22float2(*(__half2*)&raw.x);
                float2 v23 = __half22float2(*(__half2*)&raw.y);
                mx.x = fmaxf(mx.x, v01.x); mn.x = fminf(mn.x, v01.x); s1.x += v01.x; s2.x = fmaf(v01.x, v01.x, s2.x);
                mx.y = fmaxf(mx.y, v01.y); mn.y = fminf(mn.y, v01.y); s1.y += v01.y; s2.y = fmaf(v01.y, v01.y, s2.y);
                mx.z = fmaxf(mx.z, v23.x); mn.z = fminf(mn.z, v23.x); s1.z += v23.x; s2.z = fmaf(v23.x, v23.x, s2.z);
                mx.w = fmaxf(mx.w, v23.y); mn.w = fminf(mn.w, v23.y); s1.w += v23.y; s2.w = fmaf(v23.y, v23.y, s2.w);
            }
        }

        mx.x = fmaxf(mx.x, __shfl_xor_sync(0xffffffffu, mx.x, 16));
        mx.y = fmaxf(mx.y, __shfl_xor_sync(0xffffffffu, mx.y, 16));
        mx.z = fmaxf(mx.z, __shfl_xor_sync(0xffffffffu, mx.z, 16));
        mx.w = fmaxf(mx.w, __shfl_xor_sync(0xffffffffu, mx.w, 16));
        if (half == 0) {
            __half2 a01 = __floats2half2_rn(u.x + mx.x, u.y + mx.y);
            __half2 a23 = __floats2half2_rn(u.z + mx.z, u.w + mx.w);
            ((uint2*)(g_mxh + (size_t)point * O_))[c4] =
                make_uint2(*(uint32_t*)&a01, *(uint32_t*)&a23);
        }
        if (gneg) {
            mn.x = fminf(mn.x, __shfl_xor_sync(0xffffffffu, mn.x, 16));
            mn.y = fminf(mn.y, __shfl_xor_sync(0xffffffffu, mn.y, 16));
            mn.z = fminf(mn.z, __shfl_xor_sync(0xffffffffu, mn.z, 16));
            mn.w = fminf(mn.w, __shfl_xor_sync(0xffffffffu, mn.w, 16));
            if (half == 0) {
                __half2 a01 = __floats2half2_rn(u.x + mn.x, u.y + mn.y);
                __half2 a23 = __floats2half2_rn(u.z + mn.z, u.w + mn.w);
                ((uint2*)(g_mnh + (size_t)point * O_))[c4] =
                    make_uint2(*(uint32_t*)&a01, *(uint32_t*)&a23);
            }
        }

        cs1.x += 8.f * u.x + s1.x;  cs2.x += fmaf(8.f * u.x, u.x, fmaf(2.f * u.x, s1.x, s2.x));
        cs1.y += 8.f * u.y + s1.y;  cs2.y += fmaf(8.f * u.y, u.y, fmaf(2.f * u.y, s1.y, s2.y));
        cs1.z += 8.f * u.z + s1.z;  cs2.z += fmaf(8.f * u.z, u.z, fmaf(2.f * u.z, s1.z, s2.z));
        cs1.w += 8.f * u.w + s1.w;  cs2.w += fmaf(8.f * u.w, u.w, fmaf(2.f * u.w, s1.w, s2.w));
    }

    __syncthreads();
    int cb = c4 * 4;
    atomicAdd(&ssum[cb + 0], cs1.x); atomicAdd(&ssq[cb + 0], cs2.x);
    atomicAdd(&ssum[cb + 1], cs1.y); atomicAdd(&ssq[cb + 1], cs2.y);
    atomicAdd(&ssum[cb + 2], cs1.z); atomicAdd(&ssq[cb + 2], cs2.z);
    atomicAdd(&ssum[cb + 3], cs1.w); atomicAdd(&ssq[cb + 3], cs2.w);
    __syncthreads();
    if (tid < O_) {
        atomicAdd(&g_sum[tid], ssum[tid]);
        atomicAdd(&g_sq[tid],  ssq[tid]);
    }
}

// ---------------------------------------------------------------------------
// K3: fused stats + epilogue (R14 config: grid 1024 x 4 iters). PDL sync at top.
// ---------------------------------------------------------------------------
#define OUT_ITERS 4
#define OUT_STEP  (1024 * 256)     // grid * block, in 4-channel groups
__global__ __launch_bounds__(256) void k_out(const float* __restrict__ gamma,
                                             const float* __restrict__ beta,
                                             float* __restrict__ out) {
    __shared__ __align__(16) float sc[O_];
    __shared__ __align__(16) float sh[O_];
    int tid = threadIdx.x;
#if __CUDA_ARCH__ >= 900
    cudaGridDependencySynchronize();   // wait for k_gather's stats + mx/mn
#endif
    if (tid < O_) {
        float inv  = 1.0f / TOTSAMP;
        float mean = g_sum[tid] * inv;
        float var  = g_sq[tid] * inv - mean * mean;
        float s    = rsqrtf(var + BN_EPS) * gamma[tid];
        sc[tid] = s;
        sh[tid] = beta[tid] - mean * s;
    }
    __syncthreads();

    size_t base = (size_t)blockIdx.x * 256 + tid;
    int o4 = (int)(base & 15);
    float4 s4 = ((const float4*)sc)[o4];
    float4 b4 = ((const float4*)sh)[o4];
    int gneg = g_gneg;

#pragma unroll
    for (int it = 0; it < OUT_ITERS; it++) {
        size_t i4 = base + (size_t)it * OUT_STEP;
        uint2 rawA = __ldg((const uint2*)g_mxh + i4);
        float2 a01 = __half22float2(*(__half2*)&rawA.x);
        float2 a23 = __half22float2(*(__half2*)&rawA.y);
        float4 m = make_float4(a01.x, a01.y, a23.x, a23.y);
        if (gneg) {
            uint2 rawC = __ldg((const uint2*)g_mnh + i4);
            float2 c01 = __half22float2(*(__half2*)&rawC.x);
            float2 c23 = __half22float2(*(__half2*)&rawC.y);
            m.x = (s4.x >= 0.f) ? m.x : c01.x;
            m.y = (s4.y >= 0.f) ? m.y : c01.y;
            m.z = (s4.z >= 0.f) ? m.z : c23.x;
            m.w = (s4.w >= 0.f) ? m.w : c23.y;
        }
        float4 r;
        r.x = fmaxf(fmaf(m.x, s4.x, b4.x), 0.f);
        r.y = fmaxf(fmaf(m.y, s4.y, b4.y), 0.f);
        r.z = fmaxf(fmaf(m.z, s4.z, b4.z), 0.f);
        r.w = fmaxf(fmaf(m.w, s4.w, b4.w), 0.f);
        ((float4*)out)[i4] = r;
    }
}

// ---------------------------------------------------------------------------
// Launch: single stream; successors launched with programmatic stream
// serialization so their launch + independent prologue overlaps the
// predecessor's tail wave.
// ---------------------------------------------------------------------------
static void launch_pdl(const void* func, dim3 grid, dim3 block, void** args) {
    cudaLaunchConfig_t cfg = {};
    cfg.gridDim = grid;
    cfg.blockDim = block;
    static cudaLaunchAttribute attr[1];
    attr[0].id = cudaLaunchAttributeProgrammaticStreamSerialization;
    attr[0].val.programmaticStreamSerializationAllowed = 1;
    cfg.attrs = attr;
    cfg.numAttrs = 1;
    cudaLaunchKernelExC(&cfg, func, args);
}

extern "C" void kernel_launch(void* const* d_in, const int* in_sizes, int n_in,
                              void* d_out, int out_size) {
    const float* x     = (const float*)d_in[0];
    const int*   idx   = (const int*)  d_in[1];
    const float* w     = (const float*)d_in[2];
    const float* gamma = (const float*)d_in[3];
    const float* beta  = (const float*)d_in[4];
    float* out = (float*)d_out;

    k_prep<<<8, 256>>>(w, gamma);

    {
        void* args[] = {(void*)&x};
        launch_pdl((const void*)k_gemm, dim3(RTOT / 64), dim3(256), args);
    }
    {
        void* args[] = {(void*)&idx};
        launch_pdl((const void*)k_gather, dim3(RTOT / (8 * 16)), dim3(256), args);
    }
    {
        void* args[] = {(void*)&gamma, (void*)&beta, (void*)&out};
        launch_pdl((const void*)k_out, dim3(1024), dim3(256), args);
    }
}

// round 17
// speedup vs baseline: 1.0812x; 1.0135x over previous
#include <cuda_runtime.h>
#include <cuda_fp16.h>
#include <cstdint>

#define B_    4
#define N_    16384
#define C_    64
#define K_    16
#define O_    64
#define RTOT  (B_ * N_)          // 65536 rows
#define TOTSAMP 1048576.0f
#define BN_EPS 1e-5f
#define GATHER_GRID 512

__device__ __align__(16) float  g_u  [RTOT * O_];  // fp32
__device__ __align__(16) __half g_vh [RTOT * O_];  // fp16 gather operand
__device__ __align__(16) __half g_mxh[RTOT * O_];  // fp16: u + max_k v
__device__ __align__(16) __half g_mnh[RTOT * O_];  // fp16: u + min_k v
__device__ float g_sum[O_];
__device__ float g_sq[O_];
__device__ int   g_gneg;
__device__ int   g_bar;                             // grid barrier counter
// fp16 fragment-ordered split weights: [ks(4)][t(16)][lane(32)] uint2 {b0,b1}
__device__ __align__(16) uint2 g_Bh[4 * 16 * 32];
__device__ __align__(16) uint2 g_Bl[4 * 16 * 32];

// ---------------------------------------------------------------------------
// fp16 mma helper (sm_80 baseline PTX)
// ---------------------------------------------------------------------------
__device__ __forceinline__ void mma_f16(float d[4], const uint32_t a[4],
                                        const uint32_t b0, const uint32_t b1) {
    asm volatile(
        "mma.sync.aligned.m16n8k16.row.col.f32.f16.f16.f32 "
        "{%0,%1,%2,%3}, {%4,%5,%6,%7}, {%8,%9}, {%0,%1,%2,%3};"
        : "+f"(d[0]), "+f"(d[1]), "+f"(d[2]), "+f"(d[3])
        : "r"(a[0]), "r"(a[1]), "r"(a[2]), "r"(a[3]), "r"(b0), "r"(b1));
}

__device__ __forceinline__ float wprime(const float* w, int n, int k) {
    return (n < 64) ? (w[n * 128 + k] - w[n * 128 + 64 + k])
                    : w[(n - 64) * 128 + 64 + k];
}

// ---------------------------------------------------------------------------
// K0: pre-split weights + zero stats + gneg + reset grid barrier.
// ---------------------------------------------------------------------------
__global__ void k_prep(const float* __restrict__ w,
                       const float* __restrict__ gamma) {
    int i = blockIdx.x * 256 + threadIdx.x;
    if (i < 64) { g_sum[i] = 0.f; g_sq[i] = 0.f; }
    if (i == 64) {
        int neg = 0;
        for (int o = 0; o < O_; o++) neg |= (gamma[o] < 0.f);
        g_gneg = neg;
        g_bar = 0;
    }
    if (i >= 4 * 16 * 32) return;
    int l  = i & 31;
    int t  = (i >> 5) & 15;
    int ks = i >> 9;
    int n = t * 8 + (l >> 2);
    int k = ks * 16 + (l & 3) * 2;

    float v0 = wprime(w, n, k),     v1 = wprime(w, n, k + 1);
    float v2 = wprime(w, n, k + 8), v3 = wprime(w, n, k + 9);

    __half2 h01 = __floats2half2_rn(v0, v1);
    __half2 h23 = __floats2half2_rn(v2, v3);
    float2 f01 = __half22float2(h01);
    float2 f23 = __half22float2(h23);
    __half2 l01 = __floats2half2_rn(v0 - f01.x, v1 - f01.y);
    __half2 l23 = __floats2half2_rn(v2 - f23.x, v3 - f23.y);

    g_Bh[i] = make_uint2(*(uint32_t*)&h01, *(uint32_t*)&h23);
    g_Bl[i] = make_uint2(*(uint32_t*)&l01, *(uint32_t*)&l23);
}

// ---------------------------------------------------------------------------
// K1: [u|v] GEMM, fp16 m16n8k16 2-term split. PDL: stages x before gridsync.
// ---------------------------------------------------------------------------
#define XPITCH 68
__global__ __launch_bounds__(256, 3) void k_gemm(const float* __restrict__ x) {
    __shared__ float sX[64][XPITCH];

    int tid = threadIdx.x;
    int lane = tid & 31, wid = tid >> 5;
    int rg = wid & 3, cg = wid >> 2;

    int rowBase = blockIdx.x * 64;
    const float4* x4 = (const float4*)(x + (size_t)rowBase * 64);
    for (int i = tid; i < 64 * 16; i += 256) {
        int r = i >> 4, c4 = i & 15;
        float4 v = x4[i];
        float* p = &sX[r][c4 * 4];
        p[0] = v.x; p[1] = v.y; p[2] = v.z; p[3] = v.w;
    }

#if __CUDA_ARCH__ >= 900
    cudaGridDependencySynchronize();
#endif
    __syncthreads();

    float acc[8][4] = {};
    int arow = rg * 16 + (lane >> 2);
    const uint2* bhBase = g_Bh + cg * 8 * 32 + lane;
    const uint2* blBase = g_Bl + cg * 8 * 32 + lane;

#pragma unroll
    for (int ks = 0; ks < 4; ks++) {
        uint32_t ah[4], al[4];
        {
            int kc = ks * 16 + (lane & 3) * 2;
            float2 p00 = *(const float2*)&sX[arow][kc];
            float2 p10 = *(const float2*)&sX[arow + 8][kc];
            float2 p01 = *(const float2*)&sX[arow][kc + 8];
            float2 p11 = *(const float2*)&sX[arow + 8][kc + 8];
            __half2 h00 = __floats2half2_rn(p00.x, p00.y);
            __half2 h10 = __floats2half2_rn(p10.x, p10.y);
            __half2 h01 = __floats2half2_rn(p01.x, p01.y);
            __half2 h11 = __floats2half2_rn(p11.x, p11.y);
            float2 f00 = __half22float2(h00), f10 = __half22float2(h10);
            float2 f01 = __half22float2(h01), f11 = __half22float2(h11);
            __half2 l00 = __floats2half2_rn(p00.x - f00.x, p00.y - f00.y);
            __half2 l10 = __floats2half2_rn(p10.x - f10.x, p10.y - f10.y);
            __half2 l01 = __floats2half2_rn(p01.x - f01.x, p01.y - f01.y);
            __half2 l11 = __floats2half2_rn(p11.x - f11.x, p11.y - f11.y);
            ah[0] = *(uint32_t*)&h00; al[0] = *(uint32_t*)&l00;
            ah[1] = *(uint32_t*)&h10; al[1] = *(uint32_t*)&l10;
            ah[2] = *(uint32_t*)&h01; al[2] = *(uint32_t*)&l01;
            ah[3] = *(uint32_t*)&h11; al[3] = *(uint32_t*)&l11;
        }
        const uint2* bh = bhBase + ks * 16 * 32;
        const uint2* bl = blBase + ks * 16 * 32;
#pragma unroll
        for (int t = 0; t < 8; t++) {
            uint2 H = __ldg(bh + t * 32);
            uint2 L = __ldg(bl + t * 32);
            mma_f16(acc[t], ah, H.x, H.y);
            mma_f16(acc[t], ah, L.x, L.y);
            mma_f16(acc[t], al, H.x, H.y);
        }
    }

    int row = rowBase + rg * 16 + (lane >> 2);
    int col = (lane & 3) * 2;
    if (cg == 0) {
#pragma unroll
        for (int t = 0; t < 8; t++) {
            *(float2*)(g_u + (size_t)row * 64 + t * 8 + col) =
                make_float2(acc[t][0], acc[t][1]);
            *(float2*)(g_u + (size_t)(row + 8) * 64 + t * 8 + col) =
                make_float2(acc[t][2], acc[t][3]);
        }
    } else {
#pragma unroll
        for (int t = 0; t < 8; t++) {
            *(__half2*)(g_vh + (size_t)row * 64 + t * 8 + col) =
                __floats2half2_rn(acc[t][0], acc[t][1]);
            *(__half2*)(g_vh + (size_t)(row + 8) * 64 + t * 8 + col) =
                __floats2half2_rn(acc[t][2], acc[t][3]);
        }
    }
}

// ---------------------------------------------------------------------------
// K2: gather + grid barrier + fused epilogue.
// Phase 1: per-point max/min + BN partial sums (as R16).
// Barrier: atomic counter, all 512 blocks co-resident (4 blocks/SM bound).
// Phase 2: block recomputes the channel affine and applies relu-affine to its
// OWN 128 points (mx/mn re-read L2-hot), writing the final output.
// ---------------------------------------------------------------------------
__global__ __launch_bounds__(256, 4) void k_gather(const int* __restrict__ idx,
                                                   const float* __restrict__ gamma,
                                                   const float* __restrict__ beta,
                                                   float* __restrict__ out) {
    __shared__ int sIdx[8][256];
    __shared__ float ssum[O_], ssq[O_];
    __shared__ __align__(16) float sc[O_];
    __shared__ __align__(16) float sh[O_];

    int tid  = threadIdx.x;
    int lane = tid & 31;
    int half = lane >> 4;
    int c4   = lane & 15;
    int w    = tid >> 5;
    int warpId = blockIdx.x * 8 + w;
    int pbase  = warpId * 16;
    int b = pbase >> 14;
    const uint2* vb = (const uint2*)(g_vh + (size_t)b * N_ * O_);

    {
        const int4* src = (const int4*)(idx + (size_t)pbase * K_);
        ((int4*)sIdx[w])[lane]      = src[lane];
        ((int4*)sIdx[w])[lane + 32] = src[lane + 32];
    }
    if (tid < O_) { ssum[tid] = 0.f; ssq[tid] = 0.f; }

#if __CUDA_ARCH__ >= 900
    cudaGridDependencySynchronize();   // wait for k_gemm's u/v
#endif
    __syncwarp();

    const int gneg = g_gneg;

    float4 cs1 = {0, 0, 0, 0}, cs2 = {0, 0, 0, 0};

    for (int p = 0; p < 16; ++p) {
        int point = pbase + p;
        const int* sip = &sIdx[w][p * 16];

        float4 u = __ldg((const float4*)(g_u + (size_t)point * O_) + c4);

        float4 mx = make_float4(-3.4e38f, -3.4e38f, -3.4e38f, -3.4e38f);
        float4 mn = make_float4( 3.4e38f,  3.4e38f,  3.4e38f,  3.4e38f);
        float4 s1 = {0, 0, 0, 0}, s2 = {0, 0, 0, 0};

        int j[8];
#pragma unroll
        for (int s = 0; s < 8; s++) j[s] = sip[2 * s + half];

        if (!gneg) {
#pragma unroll
            for (int s = 0; s < 8; s++) {
                uint2 raw = __ldg(vb + (size_t)j[s] * 16 + c4);
                float2 v01 = __half22float2(*(__half2*)&raw.x);
                float2 v23 = __half22float2(*(__half2*)&raw.y);
                mx.x = fmaxf(mx.x, v01.x); s1.x += v01.x; s2.x = fmaf(v01.x, v01.x, s2.x);
                mx.y = fmaxf(mx.y, v01.y); s1.y += v01.y; s2.y = fmaf(v01.y, v01.y, s2.y);
                mx.z = fmaxf(mx.z, v23.x); s1.z += v23.x; s2.z = fmaf(v23.x, v23.x, s2.z);
                mx.w = fmaxf(mx.w, v23.y); s1.w += v23.y; s2.w = fmaf(v23.y, v23.y, s2.w);
            }
        } else {
#pragma unroll
            for (int s = 0; s < 8; s++) {
                uint2 raw = __ldg(vb + (size_t)j[s] * 16 + c4);
                float2 v01 = __half22float2(*(__half2*)&raw.x);
                float2 v23 = __half22float2(*(__half2*)&raw.y);
                mx.x = fmaxf(mx.x, v01.x); mn.x = fminf(mn.x, v01.x); s1.x += v01.x; s2.x = fmaf(v01.x, v01.x, s2.x);
                mx.y = fmaxf(mx.y, v01.y); mn.y = fminf(mn.y, v01.y); s1.y += v01.y; s2.y = fmaf(v01.y, v01.y, s2.y);
                mx.z = fmaxf(mx.z, v23.x); mn.z = fminf(mn.z, v23.x); s1.z += v23.x; s2.z = fmaf(v23.x, v23.x, s2.z);
                mx.w = fmaxf(mx.w, v23.y); mn.w = fminf(mn.w, v23.y); s1.w += v23.y; s2.w = fmaf(v23.y, v23.y, s2.w);
            }
        }

        mx.x = fmaxf(mx.x, __shfl_xor_sync(0xffffffffu, mx.x, 16));
        mx.y = fmaxf(mx.y, __shfl_xor_sync(0xffffffffu, mx.y, 16));
        mx.z = fmaxf(mx.z, __shfl_xor_sync(0xffffffffu, mx.z, 16));
        mx.w = fmaxf(mx.w, __shfl_xor_sync(0xffffffffu, mx.w, 16));
        if (half == 0) {
            __half2 a01 = __floats2half2_rn(u.x + mx.x, u.y + mx.y);
            __half2 a23 = __floats2half2_rn(u.z + mx.z, u.w + mx.w);
            ((uint2*)(g_mxh + (size_t)point * O_))[c4] =
                make_uint2(*(uint32_t*)&a01, *(uint32_t*)&a23);
        }
        if (gneg) {
            mn.x = fminf(mn.x, __shfl_xor_sync(0xffffffffu, mn.x, 16));
            mn.y = fminf(mn.y, __shfl_xor_sync(0xffffffffu, mn.y, 16));
            mn.z = fminf(mn.z, __shfl_xor_sync(0xffffffffu, mn.z, 16));
            mn.w = fminf(mn.w, __shfl_xor_sync(0xffffffffu, mn.w, 16));
            if (half == 0) {
                __half2 a01 = __floats2half2_rn(u.x + mn.x, u.y + mn.y);
                __half2 a23 = __floats2half2_rn(u.z + mn.z, u.w + mn.w);
                ((uint2*)(g_mnh + (size_t)point * O_))[c4] =
                    make_uint2(*(uint32_t*)&a01, *(uint32_t*)&a23);
            }
        }

        cs1.x += 8.f * u.x + s1.x;  cs2.x += fmaf(8.f * u.x, u.x, fmaf(2.f * u.x, s1.x, s2.x));
        cs1.y += 8.f * u.y + s1.y;  cs2.y += fmaf(8.f * u.y, u.y, fmaf(2.f * u.y, s1.y, s2.y));
        cs1.z += 8.f * u.z + s1.z;  cs2.z += fmaf(8.f * u.z, u.z, fmaf(2.f * u.z, s1.z, s2.z));
        cs1.w += 8.f * u.w + s1.w;  cs2.w += fmaf(8.f * u.w, u.w, fmaf(2.f * u.w, s1.w, s2.w));
    }

    __syncthreads();
    int cb = c4 * 4;
    atomicAdd(&ssum[cb + 0], cs1.x); atomicAdd(&ssq[cb + 0], cs2.x);
    atomicAdd(&ssum[cb + 1], cs1.y); atomicAdd(&ssq[cb + 1], cs2.y);
    atomicAdd(&ssum[cb + 2], cs1.z); atomicAdd(&ssq[cb + 2], cs2.z);
    atomicAdd(&ssum[cb + 3], cs1.w); atomicAdd(&ssq[cb + 3], cs2.w);
    __syncthreads();
    if (tid < O_) {
        atomicAdd(&g_sum[tid], ssum[tid]);
        atomicAdd(&g_sq[tid],  ssq[tid]);
    }

    // ---- grid-wide barrier (all 512 blocks co-resident by occupancy bound) --
    __threadfence();
    __syncthreads();
    if (tid == 0) {
        atomicAdd(&g_bar, 1);
        while (*(volatile int*)&g_bar < (int)gridDim.x) { }
    }
    __syncthreads();

    // ---- phase 2: fused epilogue for this block's 128 points ----
    if (tid < O_) {
        float inv  = 1.0f / TOTSAMP;
        float mean = (*(volatile float*)&g_sum[tid]) * inv;
        float var  = (*(volatile float*)&g_sq[tid]) * inv - mean * mean;
        float s    = rsqrtf(var + BN_EPS) * gamma[tid];
        sc[tid] = s;
        sh[tid] = beta[tid] - mean * s;
    }
    __syncthreads();

#pragma unroll
    for (int it = 0; it < 8; it++) {
        size_t i4 = (size_t)blockIdx.x * 2048 + tid + it * 256;
        int o4 = (int)(i4 & 15);
        float4 s4 = ((const float4*)sc)[o4];
        float4 b4 = ((const float4*)sh)[o4];
        uint2 rawA = __ldg((const uint2*)g_mxh + i4);
        float2 a01 = __half22float2(*(__half2*)&rawA.x);
        float2 a23 = __half22float2(*(__half2*)&rawA.y);
        float4 m = make_float4(a01.x, a01.y, a23.x, a23.y);
        if (gneg) {
            uint2 rawC = __ldg((const uint2*)g_mnh + i4);
            float2 c01 = __half22float2(*(__half2*)&rawC.x);
            float2 c23 = __half22float2(*(__half2*)&rawC.y);
            m.x = (s4.x >= 0.f) ? m.x : c01.x;
            m.y = (s4.y >= 0.f) ? m.y : c01.y;
            m.z = (s4.z >= 0.f) ? m.z : c23.x;
            m.w = (s4.w >= 0.f) ? m.w : c23.y;
        }
        float4 r;
        r.x = fmaxf(fmaf(m.x, s4.x, b4.x), 0.f);
        r.y = fmaxf(fmaf(m.y, s4.y, b4.y), 0.f);
        r.z = fmaxf(fmaf(m.z, s4.z, b4.z), 0.f);
        r.w = fmaxf(fmaf(m.w, s4.w, b4.w), 0.f);
        ((float4*)out)[i4] = r;
    }
}

// ---------------------------------------------------------------------------
// Launch: prep -> gemm (PDL) -> fused gather+epilogue (PDL).
// ---------------------------------------------------------------------------
static void launch_pdl(const void* func, dim3 grid, dim3 block, void** args) {
    cudaLaunchConfig_t cfg = {};
    cfg.gridDim = grid;
    cfg.blockDim = block;
    static cudaLaunchAttribute attr[1];
    attr[0].id = cudaLaunchAttributeProgrammaticStreamSerialization;
    attr[0].val.programmaticStreamSerializationAllowed = 1;
    cfg.attrs = attr;
    cfg.numAttrs = 1;
    cudaLaunchKernelExC(&cfg, func, args);
}

extern "C" void kernel_launch(void* const* d_in, const int* in_sizes, int n_in,
                              void* d_out, int out_size) {
    const float* x     = (const float*)d_in[0];
    const int*   idx   = (const int*)  d_in[1];
    const float* w     = (const float*)d_in[2];
    const float* gamma = (const float*)d_in[3];
    const float* beta  = (const float*)d_in[4];
    float* out = (float*)d_out;

    k_prep<<<8, 256>>>(w, gamma);

    {
        void* args[] = {(void*)&x};
        launch_pdl((const void*)k_gemm, dim3(RTOT / 64), dim3(256), args);
    }
    {
        void* args[] = {(void*)&idx, (void*)&gamma, (void*)&beta, (void*)&out};
        launch_pdl((const void*)k_gather, dim3(GATHER_GRID), dim3(256), args);
    }
}